// round 15
// baseline (speedup 1.0000x reference)
#include <cuda_runtime.h>
#include <math.h>

#define B_ 8
#define N_ 4096
#define M_ 96
#define OUTW 384          // 3 * N_ANGULAR
#define RCUT 6.0f
#define WARPS 8           // 256-thread blocks, 4096 blocks

// 16B-aligned packed positions (pre-pass output). 512 KB static scratch.
__device__ float4 g_pos4[B_ * N_];

// Fully-coalesced pack: 128 blocks x 256 threads; each block packs 256
// positions (768 floats) via smem staging. Stride-3 LDS is conflict-free
// (gcd(3,32)=1); both the LDG and STG sides are contiguous.
__global__ __launch_bounds__(256)
void pack_positions_kernel(const float* __restrict__ pos) {
    cudaTriggerProgrammaticLaunchCompletion();
    __shared__ float st[768];
    const int base = blockIdx.x * 256;          // first position of this block
    const int t = threadIdx.x;
    #pragma unroll
    for (int k = 0; k < 3; k++)
        st[k * 256 + t] = pos[(long)base * 3 + k * 256 + t];
    __syncthreads();
    g_pos4[base + t] = make_float4(st[3 * t], st[3 * t + 1], st[3 * t + 2], 0.0f);
}

// ---- cold path: K in 33..96 (essentially never; correctness only) ----
__device__ __noinline__ void fallback_sort_output(
        const float4* __restrict__ svec,
        int K, int lane, float* __restrict__ orow) {
    unsigned long long key[4];
    #pragma unroll
    for (int r = 0; r < 4; r++) {
        const int idx = lane * 4 + r;
        if (idx < K) {
            const float4 s = svec[idx];
            const float cut = 0.5f * (cospif(s.w * (1.0f / RCUT)) + 1.0f) / s.w;
            key[r] = ((unsigned long long)__float_as_uint(cut) << 32) | (unsigned)idx;
        } else {
            key[r] = 0ull;
        }
    }

    #define CE_INTRA(A, Bq, UP) {                                            \
        unsigned long long x_ = key[A], y_ = key[Bq];                        \
        bool sw_ = (UP) ? (x_ < y_) : (x_ > y_);                             \
        if (sw_) { key[A] = y_; key[Bq] = x_; } }

    #define CE_SHFL(Mm, UP) {                                                \
        const bool keepmax_ = (UP) ^ ((lane & (Mm)) != 0);                   \
        _Pragma("unroll")                                                    \
        for (int r_ = 0; r_ < 4; r_++) {                                     \
            unsigned long long o_ = __shfl_xor_sync(0xffffffffu, key[r_], (Mm)); \
            bool take_ = keepmax_ ? (o_ > key[r_]) : (o_ < key[r_]);         \
            key[r_] = take_ ? o_ : key[r_];                                  \
        } }

    CE_INTRA(0, 1, true)
    CE_INTRA(2, 3, false)
    { const bool up = ((lane & 1) == 0);
      CE_INTRA(0, 2, up) CE_INTRA(1, 3, up)
      CE_INTRA(0, 1, up) CE_INTRA(2, 3, up) }
    { const bool up = ((lane & 2) == 0);
      CE_SHFL(1, up)
      CE_INTRA(0, 2, up) CE_INTRA(1, 3, up)
      CE_INTRA(0, 1, up) CE_INTRA(2, 3, up) }
    { const bool up = ((lane & 4) == 0);
      CE_SHFL(2, up) CE_SHFL(1, up)
      CE_INTRA(0, 2, up) CE_INTRA(1, 3, up)
      CE_INTRA(0, 1, up) CE_INTRA(2, 3, up) }
    { const bool up = ((lane & 8) == 0);
      CE_SHFL(4, up) CE_SHFL(2, up) CE_SHFL(1, up)
      CE_INTRA(0, 2, up) CE_INTRA(1, 3, up)
      CE_INTRA(0, 1, up) CE_INTRA(2, 3, up) }
    { const bool up = ((lane & 16) == 0);
      CE_SHFL(8, up) CE_SHFL(4, up) CE_SHFL(2, up) CE_SHFL(1, up)
      CE_INTRA(0, 2, up) CE_INTRA(1, 3, up)
      CE_INTRA(0, 1, up) CE_INTRA(2, 3, up) }
    { CE_SHFL(16, true) CE_SHFL(8, true) CE_SHFL(4, true) CE_SHFL(2, true) CE_SHFL(1, true)
      CE_INTRA(0, 2, true) CE_INTRA(1, 3, true)
      CE_INTRA(0, 1, true) CE_INTRA(2, 3, true) }

    if (lane < 24) {
        float v[12];
        #pragma unroll
        for (int r = 0; r < 4; r++) {
            const int p = lane * 4 + r;
            if (p < K) {
                const int c = (int)(key[r] & 127u);
                const float4 s = svec[c];
                const float cut = 0.5f * (cospif(s.w * (1.0f / RCUT)) + 1.0f) / s.w;
                v[r * 3 + 0] = cut * s.x;
                v[r * 3 + 1] = cut * s.y;
                v[r * 3 + 2] = cut * s.z;
            } else {
                v[r * 3 + 0] = 0.f; v[r * 3 + 1] = 0.f; v[r * 3 + 2] = 0.f;
            }
        }
        float4* o4 = reinterpret_cast<float4*>(orow + lane * 12);
        o4[0] = make_float4(v[0], v[1], v[2],  v[3]);
        o4[1] = make_float4(v[4], v[5], v[6],  v[7]);
        o4[2] = make_float4(v[8], v[9], v[10], v[11]);
    } else {
        const float4 z = make_float4(0.f, 0.f, 0.f, 0.f);
        float4* o4 = reinterpret_cast<float4*>(orow + 288 + (lane - 24) * 12);
        o4[0] = z; o4[1] = z; o4[2] = z;
    }
}

__global__ __launch_bounds__(256, 5)
void deepmd_angular_kernel(const float* __restrict__ pos,
                           const float* __restrict__ cell,
                           const float* __restrict__ offs,
                           const float* __restrict__ mask,
                           const int*   __restrict__ neigh,
                           float* __restrict__ out) {
    const int warp = threadIdx.x >> 5;
    const int lane = threadIdx.x & 31;
    const int row  = blockIdx.x * WARPS + warp;   // b*N_ + n
    const int b    = row >> 12;                   // N_ = 4096

    __shared__ float4 svec[WARPS][M_];   // compacted survivors only

    const float* pi = pos + (long)row * 3;
    const float pix = pi[0], piy = pi[1], piz = pi[2];

    unsigned nzm = 0;                    // 4 nz bits for this lane's neighbors
    float dx4[4], dy4[4], dz4[4], dd4[4];

    // ---- prologue: everything independent of g_pos4 ----
    int   j4[4]  = {0, 0, 0, 0};
    float m4[4]  = {0.f, 0.f, 0.f, 0.f};
    float ocx[4], ocy[4], ocz[4];

    if (lane < 24) {
        const long base = (long)row * M_ + lane * 4;
        const int4   jj = *reinterpret_cast<const int4*>(neigh + base);
        const float4 mm = *reinterpret_cast<const float4*>(mask + base);
        const float4* op = reinterpret_cast<const float4*>(offs + base * 3);
        const float4 oA = op[0], oB = op[1], oC = op[2];

        const float* cb = cell + b * 9;
        const float c00 = cb[0], c01 = cb[1], c02 = cb[2];
        const float c10 = cb[3], c11 = cb[4], c12 = cb[5];
        const float c20 = cb[6], c21 = cb[7], c22 = cb[8];

        const float ox[4] = {oA.x, oA.w, oB.z, oC.y};
        const float oy[4] = {oA.y, oB.x, oB.w, oC.z};
        const float oz[4] = {oA.z, oB.y, oC.x, oC.w};
        #pragma unroll
        for (int r = 0; r < 4; r++) {
            ocx[r] = ox[r] * c00 + oy[r] * c10 + oz[r] * c20 - pix;
            ocy[r] = ox[r] * c01 + oy[r] * c11 + oz[r] * c21 - piy;
            ocz[r] = ox[r] * c02 + oy[r] * c12 + oz[r] * c22 - piz;
        }

        j4[0] = jj.x; j4[1] = jj.y; j4[2] = jj.z; j4[3] = jj.w;
        m4[0] = mm.x; m4[1] = mm.y; m4[2] = mm.z; m4[3] = mm.w;
    }

    // wait for pack_positions_kernel's writes to g_pos4 (PDL)
    cudaGridDependencySynchronize();

    if (lane < 24) {
        // batched gathers: ONE aligned LDG.128 per neighbor, all 4 in flight
        float4 pj4[4];
        #pragma unroll
        for (int r = 0; r < 4; r++)
            pj4[r] = __ldg(&g_pos4[b * N_ + j4[r]]);

        #pragma unroll
        for (int r = 0; r < 4; r++) {
            dx4[r] = pj4[r].x + ocx[r];
            dy4[r] = pj4[r].y + ocy[r];
            dz4[r] = pj4[r].z + ocz[r];
            dd4[r] = sqrtf(fmaf(dx4[r], dx4[r],
                      fmaf(dy4[r], dy4[r], fmaf(dz4[r], dz4[r], 1e-12f))));
            // cut > 0 <=> mask!=0 && d < RCUT (1+cos can't round to 0 for d<6)
            if (m4[r] != 0.0f && dd4[r] < RCUT) nzm |= (1u << r);
        }
    }

    // ---- ballots at the END (no latency exposure mid-gather) ----
    const unsigned lt = (1u << lane) - 1u;
    unsigned bal[4];
    int K = 0;
    #pragma unroll
    for (int r = 0; r < 4; r++) {
        bal[r] = __ballot_sync(0xffffffffu, (nzm >> r) & 1u);
        K += __popc(bal[r]);
    }

    // survivors write ONE compacted float4 each (~K total STS per row)
    {
        int pref = 0;
        #pragma unroll
        for (int r = 0; r < 4; r++) {
            if ((nzm >> r) & 1u) {
                const int p = pref + __popc(bal[r] & lt);
                svec[warp][p] = make_float4(dx4[r], dy4[r], dz4[r], dd4[r]);
            }
            pref += __popc(bal[r]);
        }
    }
    __syncwarp();

    float* orow = out + (long)row * OUTW;

    if (K <= 32) {
        // ---- pass 2: survivors only ----
        float vx = 0.f, vy = 0.f, vz = 0.f;
        unsigned long long k0 = 0ull;
        if (lane < K) {
            const float4 s = svec[warp][lane];
            const float cut = 0.5f * (cospif(s.w * (1.0f / RCUT)) + 1.0f) / s.w; // bit-identical
            vx = cut * s.x; vy = cut * s.y; vz = cut * s.z;
            // ties among nonzero cuts => identical (j,offset) => identical
            // vectors; tie order immaterial -> low bits only need uniqueness.
            k0 = ((unsigned long long)__float_as_uint(cut) << 32) | (unsigned)lane;
        }

        #define CEW(J, UPX) {                                                \
            const bool keepmax = (UPX) ^ ((lane & (J)) != 0);                \
            const unsigned long long o = __shfl_xor_sync(0xffffffffu, k0, (J)); \
            const bool take = keepmax ? (o > k0) : (o < k0);                 \
            k0 = take ? o : k0; }

        if (K <= 8) {
            // 8-wide bitonic (6 CEs); lanes >= 8 carry zeros harmlessly
            { const bool up = ((lane & 2)  == 0); CEW(1, up) }
            { const bool up = ((lane & 4)  == 0); CEW(2, up) CEW(1, up) }
            { const bool up = ((lane & 8)  == 0); CEW(4, up) CEW(2, up) CEW(1, up) }
        } else if (K <= 16) {
            { const bool up = ((lane & 2)  == 0); CEW(1, up) }
            { const bool up = ((lane & 4)  == 0); CEW(2, up) CEW(1, up) }
            { const bool up = ((lane & 8)  == 0); CEW(4, up) CEW(2, up) CEW(1, up) }
            { const bool up = ((lane & 16) == 0); CEW(8, up) CEW(4, up) CEW(2, up) CEW(1, up) }
        } else {
            { const bool up = ((lane & 2)  == 0); CEW(1, up) }
            { const bool up = ((lane & 4)  == 0); CEW(2, up) CEW(1, up) }
            { const bool up = ((lane & 8)  == 0); CEW(4, up) CEW(2, up) CEW(1, up) }
            { const bool up = ((lane & 16) == 0); CEW(8, up) CEW(4, up) CEW(2, up) CEW(1, up) }
            { CEW(16, true) CEW(8, true) CEW(4, true) CEW(2, true) CEW(1, true) }
        }

        // gather sorted vectors via shuffle (source lane = survivor id)
        const int c = (int)(k0 & 63u);
        const float sx = __shfl_sync(0xffffffffu, vx, c);
        const float sy = __shfl_sync(0xffffffffu, vy, c);
        const float sz = __shfl_sync(0xffffffffu, vz, c);
        if (lane < K) {
            orow[3 * lane + 0] = sx;
            orow[3 * lane + 1] = sy;
            orow[3 * lane + 2] = sz;
        }
        // zero-fill [3K, 384): scalar head (lanes 0..2 in parallel), then float4s
        const int start = 3 * K;
        const int f0 = (start + 3) >> 2;
        const int head = 4 * f0 - start;          // 0..3 scalar zeros needed
        if (lane < head) orow[start + lane] = 0.0f;
        const float4 z = make_float4(0.f, 0.f, 0.f, 0.f);
        for (int f = f0 + lane; f < OUTW / 4; f += 32)
            reinterpret_cast<float4*>(orow)[f] = z;
    } else {
        fallback_sort_output(&svec[warp][0], K, lane, orow);
    }
}

extern "C" void kernel_launch(void* const* d_in, const int* in_sizes, int n_in,
                              void* d_out, int out_size) {
    const float* positions = (const float*)d_in[0];
    const float* cell      = (const float*)d_in[1];
    const float* offsets   = (const float*)d_in[2];
    const float* mask      = (const float*)d_in[3];
    const int*   neighbors = (const int*)d_in[4];
    float* out = (float*)d_out;

    // coalesced pack pass (triggers programmatic completion immediately)
    pack_positions_kernel<<<(B_ * N_) / 256, 256>>>(positions);

    // main kernel with PDL dependency: launches while pack runs, syncs
    // before reading g_pos4.
    cudaLaunchConfig_t cfg = {};
    cfg.gridDim  = dim3((B_ * N_) / WARPS);
    cfg.blockDim = dim3(256);
    cudaLaunchAttribute attr[1];
    attr[0].id = cudaLaunchAttributeProgrammaticStreamSerialization;
    attr[0].val.programmaticStreamSerializationAllowed = 1;
    cfg.attrs = attr;
    cfg.numAttrs = 1;
    cudaLaunchKernelEx(&cfg, deepmd_angular_kernel,
                       positions, cell, offsets, mask, neighbors, out);
}

// round 16
// speedup vs baseline: 1.0794x; 1.0794x over previous
#include <cuda_runtime.h>
#include <math.h>

#define B_ 8
#define N_ 4096
#define M_ 96
#define OUTW 384          // 3 * N_ANGULAR
#define RCUT 6.0f
#define WARPS 4

// 16B-aligned packed positions (pre-pass output). 512 KB static scratch.
__device__ float4 g_pos4[B_ * N_];

// Fully-coalesced pack: 128 blocks x 256 threads; each block packs 256
// positions (768 floats) via smem staging. Stride-3 LDS is conflict-free
// (gcd(3,32)=1); both the LDG and STG sides are contiguous.
__global__ __launch_bounds__(256)
void pack_positions_kernel(const float* __restrict__ pos) {
    cudaTriggerProgrammaticLaunchCompletion();
    __shared__ float st[768];
    const int base = blockIdx.x * 256;          // first position of this block
    const int t = threadIdx.x;
    #pragma unroll
    for (int k = 0; k < 3; k++)
        st[k * 256 + t] = pos[(long)base * 3 + k * 256 + t];
    __syncthreads();
    g_pos4[base + t] = make_float4(st[3 * t], st[3 * t + 1], st[3 * t + 2], 0.0f);
}

// ---- cold path: K in 33..96 (essentially never; correctness only) ----
__device__ __noinline__ void fallback_sort_output(
        const float4* __restrict__ svec,
        int K, int lane, float* __restrict__ orow) {
    unsigned long long key[4];
    #pragma unroll
    for (int r = 0; r < 4; r++) {
        const int idx = lane * 4 + r;
        if (idx < K) {
            const float4 s = svec[idx];
            const float cut = 0.5f * (cospif(s.w * (1.0f / RCUT)) + 1.0f) / s.w;
            key[r] = ((unsigned long long)__float_as_uint(cut) << 32) | (unsigned)idx;
        } else {
            key[r] = 0ull;
        }
    }

    #define CE_INTRA(A, Bq, UP) {                                            \
        unsigned long long x_ = key[A], y_ = key[Bq];                        \
        bool sw_ = (UP) ? (x_ < y_) : (x_ > y_);                             \
        if (sw_) { key[A] = y_; key[Bq] = x_; } }

    #define CE_SHFL(Mm, UP) {                                                \
        const bool keepmax_ = (UP) ^ ((lane & (Mm)) != 0);                   \
        _Pragma("unroll")                                                    \
        for (int r_ = 0; r_ < 4; r_++) {                                     \
            unsigned long long o_ = __shfl_xor_sync(0xffffffffu, key[r_], (Mm)); \
            bool take_ = keepmax_ ? (o_ > key[r_]) : (o_ < key[r_]);         \
            key[r_] = take_ ? o_ : key[r_];                                  \
        } }

    CE_INTRA(0, 1, true)
    CE_INTRA(2, 3, false)
    { const bool up = ((lane & 1) == 0);
      CE_INTRA(0, 2, up) CE_INTRA(1, 3, up)
      CE_INTRA(0, 1, up) CE_INTRA(2, 3, up) }
    { const bool up = ((lane & 2) == 0);
      CE_SHFL(1, up)
      CE_INTRA(0, 2, up) CE_INTRA(1, 3, up)
      CE_INTRA(0, 1, up) CE_INTRA(2, 3, up) }
    { const bool up = ((lane & 4) == 0);
      CE_SHFL(2, up) CE_SHFL(1, up)
      CE_INTRA(0, 2, up) CE_INTRA(1, 3, up)
      CE_INTRA(0, 1, up) CE_INTRA(2, 3, up) }
    { const bool up = ((lane & 8) == 0);
      CE_SHFL(4, up) CE_SHFL(2, up) CE_SHFL(1, up)
      CE_INTRA(0, 2, up) CE_INTRA(1, 3, up)
      CE_INTRA(0, 1, up) CE_INTRA(2, 3, up) }
    { const bool up = ((lane & 16) == 0);
      CE_SHFL(8, up) CE_SHFL(4, up) CE_SHFL(2, up) CE_SHFL(1, up)
      CE_INTRA(0, 2, up) CE_INTRA(1, 3, up)
      CE_INTRA(0, 1, up) CE_INTRA(2, 3, up) }
    { CE_SHFL(16, true) CE_SHFL(8, true) CE_SHFL(4, true) CE_SHFL(2, true) CE_SHFL(1, true)
      CE_INTRA(0, 2, true) CE_INTRA(1, 3, true)
      CE_INTRA(0, 1, true) CE_INTRA(2, 3, true) }

    if (lane < 24) {
        float v[12];
        #pragma unroll
        for (int r = 0; r < 4; r++) {
            const int p = lane * 4 + r;
            if (p < K) {
                const int c = (int)(key[r] & 127u);
                const float4 s = svec[c];
                const float cut = 0.5f * (cospif(s.w * (1.0f / RCUT)) + 1.0f) / s.w;
                v[r * 3 + 0] = cut * s.x;
                v[r * 3 + 1] = cut * s.y;
                v[r * 3 + 2] = cut * s.z;
            } else {
                v[r * 3 + 0] = 0.f; v[r * 3 + 1] = 0.f; v[r * 3 + 2] = 0.f;
            }
        }
        float4* o4 = reinterpret_cast<float4*>(orow + lane * 12);
        o4[0] = make_float4(v[0], v[1], v[2],  v[3]);
        o4[1] = make_float4(v[4], v[5], v[6],  v[7]);
        o4[2] = make_float4(v[8], v[9], v[10], v[11]);
    } else {
        const float4 z = make_float4(0.f, 0.f, 0.f, 0.f);
        float4* o4 = reinterpret_cast<float4*>(orow + 288 + (lane - 24) * 12);
        o4[0] = z; o4[1] = z; o4[2] = z;
    }
}

__global__ __launch_bounds__(128, 10)
void deepmd_angular_kernel(const float* __restrict__ pos,
                           const float* __restrict__ cell,
                           const float* __restrict__ offs,
                           const float* __restrict__ mask,
                           const int*   __restrict__ neigh,
                           float* __restrict__ out) {
    const int warp = threadIdx.x >> 5;
    const int lane = threadIdx.x & 31;
    const int row  = blockIdx.x * WARPS + warp;   // b*N_ + n
    const int b    = row >> 12;                   // N_ = 4096

    __shared__ float4 svec[WARPS][M_];   // compacted survivors only

    const float* pi = pos + (long)row * 3;
    const float pix = pi[0], piy = pi[1], piz = pi[2];

    unsigned nzm = 0;                    // 4 nz bits for this lane's neighbors
    float dx4[4], dy4[4], dz4[4], dd4[4];

    // ---- prologue: everything independent of g_pos4 ----
    int   j4[4]  = {0, 0, 0, 0};
    float m4[4]  = {0.f, 0.f, 0.f, 0.f};
    float ocx[4], ocy[4], ocz[4];

    if (lane < 24) {
        const long base = (long)row * M_ + lane * 4;
        const int4   jj = *reinterpret_cast<const int4*>(neigh + base);
        const float4 mm = *reinterpret_cast<const float4*>(mask + base);
        const float4* op = reinterpret_cast<const float4*>(offs + base * 3);
        const float4 oA = op[0], oB = op[1], oC = op[2];

        const float* cb = cell + b * 9;
        const float c00 = cb[0], c01 = cb[1], c02 = cb[2];
        const float c10 = cb[3], c11 = cb[4], c12 = cb[5];
        const float c20 = cb[6], c21 = cb[7], c22 = cb[8];

        const float ox[4] = {oA.x, oA.w, oB.z, oC.y};
        const float oy[4] = {oA.y, oB.x, oB.w, oC.z};
        const float oz[4] = {oA.z, oB.y, oC.x, oC.w};
        #pragma unroll
        for (int r = 0; r < 4; r++) {
            ocx[r] = ox[r] * c00 + oy[r] * c10 + oz[r] * c20 - pix;
            ocy[r] = ox[r] * c01 + oy[r] * c11 + oz[r] * c21 - piy;
            ocz[r] = ox[r] * c02 + oy[r] * c12 + oz[r] * c22 - piz;
        }

        j4[0] = jj.x; j4[1] = jj.y; j4[2] = jj.z; j4[3] = jj.w;
        m4[0] = mm.x; m4[1] = mm.y; m4[2] = mm.z; m4[3] = mm.w;
    }

    // wait for pack_positions_kernel's writes to g_pos4 (PDL)
    cudaGridDependencySynchronize();

    if (lane < 24) {
        // batched gathers: ONE aligned LDG.128 per neighbor, all 4 in flight
        float4 pj4[4];
        #pragma unroll
        for (int r = 0; r < 4; r++)
            pj4[r] = __ldg(&g_pos4[b * N_ + j4[r]]);

        #pragma unroll
        for (int r = 0; r < 4; r++) {
            dx4[r] = pj4[r].x + ocx[r];
            dy4[r] = pj4[r].y + ocy[r];
            dz4[r] = pj4[r].z + ocz[r];
            dd4[r] = sqrtf(fmaf(dx4[r], dx4[r],
                      fmaf(dy4[r], dy4[r], fmaf(dz4[r], dz4[r], 1e-12f))));
            // cut > 0 <=> mask!=0 && d < RCUT (1+cos can't round to 0 for d<6)
            if (m4[r] != 0.0f && dd4[r] < RCUT) nzm |= (1u << r);
        }
    }

    // ---- ballots at the END (no latency exposure mid-gather) ----
    const unsigned lt = (1u << lane) - 1u;
    unsigned bal[4];
    int K = 0;
    #pragma unroll
    for (int r = 0; r < 4; r++) {
        bal[r] = __ballot_sync(0xffffffffu, (nzm >> r) & 1u);
        K += __popc(bal[r]);
    }

    // survivors write ONE compacted float4 each (~K total STS per row)
    {
        int pref = 0;
        #pragma unroll
        for (int r = 0; r < 4; r++) {
            if ((nzm >> r) & 1u) {
                const int p = pref + __popc(bal[r] & lt);
                svec[warp][p] = make_float4(dx4[r], dy4[r], dz4[r], dd4[r]);
            }
            pref += __popc(bal[r]);
        }
    }
    __syncwarp();

    float* orow = out + (long)row * OUTW;

    if (K <= 32) {
        // ---- pass 2: survivors only ----
        float vx = 0.f, vy = 0.f, vz = 0.f;
        unsigned long long k0 = 0ull;
        if (lane < K) {
            const float4 s = svec[warp][lane];
            const float cut = 0.5f * (cospif(s.w * (1.0f / RCUT)) + 1.0f) / s.w; // bit-identical
            vx = cut * s.x; vy = cut * s.y; vz = cut * s.z;
            // ties among nonzero cuts => identical (j,offset) => identical
            // vectors; tie order immaterial -> low bits only need uniqueness.
            k0 = ((unsigned long long)__float_as_uint(cut) << 32) | (unsigned)lane;
        }

        #define CEW(J, UPX) {                                                \
            const bool keepmax = (UPX) ^ ((lane & (J)) != 0);                \
            const unsigned long long o = __shfl_xor_sync(0xffffffffu, k0, (J)); \
            const bool take = keepmax ? (o > k0) : (o < k0);                 \
            k0 = take ? o : k0; }

        if (K <= 8) {
            // 8-wide bitonic (6 CEs); lanes >= 8 carry zeros harmlessly
            { const bool up = ((lane & 2)  == 0); CEW(1, up) }
            { const bool up = ((lane & 4)  == 0); CEW(2, up) CEW(1, up) }
            { const bool up = ((lane & 8)  == 0); CEW(4, up) CEW(2, up) CEW(1, up) }
        } else if (K <= 16) {
            { const bool up = ((lane & 2)  == 0); CEW(1, up) }
            { const bool up = ((lane & 4)  == 0); CEW(2, up) CEW(1, up) }
            { const bool up = ((lane & 8)  == 0); CEW(4, up) CEW(2, up) CEW(1, up) }
            { const bool up = ((lane & 16) == 0); CEW(8, up) CEW(4, up) CEW(2, up) CEW(1, up) }
        } else {
            { const bool up = ((lane & 2)  == 0); CEW(1, up) }
            { const bool up = ((lane & 4)  == 0); CEW(2, up) CEW(1, up) }
            { const bool up = ((lane & 8)  == 0); CEW(4, up) CEW(2, up) CEW(1, up) }
            { const bool up = ((lane & 16) == 0); CEW(8, up) CEW(4, up) CEW(2, up) CEW(1, up) }
            { CEW(16, true) CEW(8, true) CEW(4, true) CEW(2, true) CEW(1, true) }
        }

        // gather sorted vectors via shuffle (source lane = survivor id)
        const int c = (int)(k0 & 63u);
        const float sx = __shfl_sync(0xffffffffu, vx, c);
        const float sy = __shfl_sync(0xffffffffu, vy, c);
        const float sz = __shfl_sync(0xffffffffu, vz, c);
        if (lane < K) {
            orow[3 * lane + 0] = sx;
            orow[3 * lane + 1] = sy;
            orow[3 * lane + 2] = sz;
        }
        // zero-fill [3K, 384): scalar head (lanes 0..2 in parallel), then float4s
        const int start = 3 * K;
        const int f0 = (start + 3) >> 2;
        const int head = 4 * f0 - start;          // 0..3 scalar zeros needed
        if (lane < head) orow[start + lane] = 0.0f;
        const float4 z = make_float4(0.f, 0.f, 0.f, 0.f);
        for (int f = f0 + lane; f < OUTW / 4; f += 32)
            reinterpret_cast<float4*>(orow)[f] = z;
    } else {
        fallback_sort_output(&svec[warp][0], K, lane, orow);
    }
}

extern "C" void kernel_launch(void* const* d_in, const int* in_sizes, int n_in,
                              void* d_out, int out_size) {
    const float* positions = (const float*)d_in[0];
    const float* cell      = (const float*)d_in[1];
    const float* offsets   = (const float*)d_in[2];
    const float* mask      = (const float*)d_in[3];
    const int*   neighbors = (const int*)d_in[4];
    float* out = (float*)d_out;

    // coalesced pack pass (triggers programmatic completion immediately)
    pack_positions_kernel<<<(B_ * N_) / 256, 256>>>(positions);

    // main kernel with PDL dependency: launches while pack runs, syncs
    // before reading g_pos4.
    cudaLaunchConfig_t cfg = {};
    cfg.gridDim  = dim3((B_ * N_) / WARPS);
    cfg.blockDim = dim3(128);
    cudaLaunchAttribute attr[1];
    attr[0].id = cudaLaunchAttributeProgrammaticStreamSerialization;
    attr[0].val.programmaticStreamSerializationAllowed = 1;
    cfg.attrs = attr;
    cfg.numAttrs = 1;
    cudaLaunchKernelEx(&cfg, deepmd_angular_kernel,
                       positions, cell, offsets, mask, neighbors, out);
}

// round 17
// speedup vs baseline: 1.2541x; 1.1618x over previous
#include <cuda_runtime.h>
#include <math.h>

#define B_ 8
#define N_ 4096
#define M_ 96
#define OUTW 384          // 3 * N_ANGULAR
#define RCUT 6.0f
#define WARPS 4

// streaming (evict-first) stores: output is write-once, never re-read
__device__ __forceinline__ void stcs_f(float* p, float v) {
    asm volatile("st.global.cs.f32 [%0], %1;" :: "l"(p), "f"(v) : "memory");
}
__device__ __forceinline__ void stcs_f4(float4* p, float4 v) {
    asm volatile("st.global.cs.v4.f32 [%0], {%1,%2,%3,%4};"
                 :: "l"(p), "f"(v.x), "f"(v.y), "f"(v.z), "f"(v.w) : "memory");
}

// 16B-aligned packed positions (pre-pass output). 512 KB static scratch.
__device__ float4 g_pos4[B_ * N_];

// Fully-coalesced pack: 128 blocks x 256 threads; each block packs 256
// positions (768 floats) via smem staging. Stride-3 LDS is conflict-free
// (gcd(3,32)=1); both the LDG and STG sides are contiguous.
__global__ __launch_bounds__(256)
void pack_positions_kernel(const float* __restrict__ pos) {
    cudaTriggerProgrammaticLaunchCompletion();
    __shared__ float st[768];
    const int base = blockIdx.x * 256;          // first position of this block
    const int t = threadIdx.x;
    #pragma unroll
    for (int k = 0; k < 3; k++)
        st[k * 256 + t] = pos[(long)base * 3 + k * 256 + t];
    __syncthreads();
    g_pos4[base + t] = make_float4(st[3 * t], st[3 * t + 1], st[3 * t + 2], 0.0f);
}

// ---- cold path: K in 33..96 (essentially never; correctness only) ----
__device__ __noinline__ void fallback_sort_output(
        const float4* __restrict__ svec,
        int K, int lane, float* __restrict__ orow) {
    unsigned long long key[4];
    #pragma unroll
    for (int r = 0; r < 4; r++) {
        const int idx = lane * 4 + r;
        if (idx < K) {
            const float4 s = svec[idx];
            const float cut = 0.5f * (cospif(s.w * (1.0f / RCUT)) + 1.0f) / s.w;
            key[r] = ((unsigned long long)__float_as_uint(cut) << 32) | (unsigned)idx;
        } else {
            key[r] = 0ull;
        }
    }

    #define CE_INTRA(A, Bq, UP) {                                            \
        unsigned long long x_ = key[A], y_ = key[Bq];                        \
        bool sw_ = (UP) ? (x_ < y_) : (x_ > y_);                             \
        if (sw_) { key[A] = y_; key[Bq] = x_; } }

    #define CE_SHFL(Mm, UP) {                                                \
        const bool keepmax_ = (UP) ^ ((lane & (Mm)) != 0);                   \
        _Pragma("unroll")                                                    \
        for (int r_ = 0; r_ < 4; r_++) {                                     \
            unsigned long long o_ = __shfl_xor_sync(0xffffffffu, key[r_], (Mm)); \
            bool take_ = keepmax_ ? (o_ > key[r_]) : (o_ < key[r_]);         \
            key[r_] = take_ ? o_ : key[r_];                                  \
        } }

    CE_INTRA(0, 1, true)
    CE_INTRA(2, 3, false)
    { const bool up = ((lane & 1) == 0);
      CE_INTRA(0, 2, up) CE_INTRA(1, 3, up)
      CE_INTRA(0, 1, up) CE_INTRA(2, 3, up) }
    { const bool up = ((lane & 2) == 0);
      CE_SHFL(1, up)
      CE_INTRA(0, 2, up) CE_INTRA(1, 3, up)
      CE_INTRA(0, 1, up) CE_INTRA(2, 3, up) }
    { const bool up = ((lane & 4) == 0);
      CE_SHFL(2, up) CE_SHFL(1, up)
      CE_INTRA(0, 2, up) CE_INTRA(1, 3, up)
      CE_INTRA(0, 1, up) CE_INTRA(2, 3, up) }
    { const bool up = ((lane & 8) == 0);
      CE_SHFL(4, up) CE_SHFL(2, up) CE_SHFL(1, up)
      CE_INTRA(0, 2, up) CE_INTRA(1, 3, up)
      CE_INTRA(0, 1, up) CE_INTRA(2, 3, up) }
    { const bool up = ((lane & 16) == 0);
      CE_SHFL(8, up) CE_SHFL(4, up) CE_SHFL(2, up) CE_SHFL(1, up)
      CE_INTRA(0, 2, up) CE_INTRA(1, 3, up)
      CE_INTRA(0, 1, up) CE_INTRA(2, 3, up) }
    { CE_SHFL(16, true) CE_SHFL(8, true) CE_SHFL(4, true) CE_SHFL(2, true) CE_SHFL(1, true)
      CE_INTRA(0, 2, true) CE_INTRA(1, 3, true)
      CE_INTRA(0, 1, true) CE_INTRA(2, 3, true) }

    if (lane < 24) {
        float v[12];
        #pragma unroll
        for (int r = 0; r < 4; r++) {
            const int p = lane * 4 + r;
            if (p < K) {
                const int c = (int)(key[r] & 127u);
                const float4 s = svec[c];
                const float cut = 0.5f * (cospif(s.w * (1.0f / RCUT)) + 1.0f) / s.w;
                v[r * 3 + 0] = cut * s.x;
                v[r * 3 + 1] = cut * s.y;
                v[r * 3 + 2] = cut * s.z;
            } else {
                v[r * 3 + 0] = 0.f; v[r * 3 + 1] = 0.f; v[r * 3 + 2] = 0.f;
            }
        }
        float4* o4 = reinterpret_cast<float4*>(orow + lane * 12);
        stcs_f4(o4 + 0, make_float4(v[0], v[1], v[2],  v[3]));
        stcs_f4(o4 + 1, make_float4(v[4], v[5], v[6],  v[7]));
        stcs_f4(o4 + 2, make_float4(v[8], v[9], v[10], v[11]));
    } else {
        const float4 z = make_float4(0.f, 0.f, 0.f, 0.f);
        float4* o4 = reinterpret_cast<float4*>(orow + 288 + (lane - 24) * 12);
        stcs_f4(o4 + 0, z); stcs_f4(o4 + 1, z); stcs_f4(o4 + 2, z);
    }
}

__global__ __launch_bounds__(128, 10)
void deepmd_angular_kernel(const float* __restrict__ pos,
                           const float* __restrict__ cell,
                           const float* __restrict__ offs,
                           const float* __restrict__ mask,
                           const int*   __restrict__ neigh,
                           float* __restrict__ out) {
    const int warp = threadIdx.x >> 5;
    const int lane = threadIdx.x & 31;
    const int row  = blockIdx.x * WARPS + warp;   // b*N_ + n
    const int b    = row >> 12;                   // N_ = 4096

    __shared__ float4 svec[WARPS][M_];   // compacted survivors only

    const float* pi = pos + (long)row * 3;
    const float pix = pi[0], piy = pi[1], piz = pi[2];

    unsigned nzm = 0;                    // 4 nz bits for this lane's neighbors
    float dx4[4], dy4[4], dz4[4], dd4[4];

    // ---- prologue: everything independent of g_pos4 ----
    int   j4[4]  = {0, 0, 0, 0};
    float m4[4]  = {0.f, 0.f, 0.f, 0.f};
    float ocx[4], ocy[4], ocz[4];

    if (lane < 24) {
        const long base = (long)row * M_ + lane * 4;
        const int4   jj = *reinterpret_cast<const int4*>(neigh + base);
        const float4 mm = *reinterpret_cast<const float4*>(mask + base);
        const float4* op = reinterpret_cast<const float4*>(offs + base * 3);
        const float4 oA = op[0], oB = op[1], oC = op[2];

        const float* cb = cell + b * 9;
        const float c00 = cb[0], c01 = cb[1], c02 = cb[2];
        const float c10 = cb[3], c11 = cb[4], c12 = cb[5];
        const float c20 = cb[6], c21 = cb[7], c22 = cb[8];

        const float ox[4] = {oA.x, oA.w, oB.z, oC.y};
        const float oy[4] = {oA.y, oB.x, oB.w, oC.z};
        const float oz[4] = {oA.z, oB.y, oC.x, oC.w};
        #pragma unroll
        for (int r = 0; r < 4; r++) {
            ocx[r] = ox[r] * c00 + oy[r] * c10 + oz[r] * c20 - pix;
            ocy[r] = ox[r] * c01 + oy[r] * c11 + oz[r] * c21 - piy;
            ocz[r] = ox[r] * c02 + oy[r] * c12 + oz[r] * c22 - piz;
        }

        j4[0] = jj.x; j4[1] = jj.y; j4[2] = jj.z; j4[3] = jj.w;
        m4[0] = mm.x; m4[1] = mm.y; m4[2] = mm.z; m4[3] = mm.w;
    }

    // wait for pack_positions_kernel's writes to g_pos4 (PDL)
    cudaGridDependencySynchronize();

    if (lane < 24) {
        // batched gathers: ONE aligned LDG.128 per neighbor, all 4 in flight
        float4 pj4[4];
        #pragma unroll
        for (int r = 0; r < 4; r++)
            pj4[r] = __ldg(&g_pos4[b * N_ + j4[r]]);

        #pragma unroll
        for (int r = 0; r < 4; r++) {
            dx4[r] = pj4[r].x + ocx[r];
            dy4[r] = pj4[r].y + ocy[r];
            dz4[r] = pj4[r].z + ocz[r];
            dd4[r] = sqrtf(fmaf(dx4[r], dx4[r],
                      fmaf(dy4[r], dy4[r], fmaf(dz4[r], dz4[r], 1e-12f))));
            // cut > 0 <=> mask!=0 && d < RCUT (1+cos can't round to 0 for d<6)
            if (m4[r] != 0.0f && dd4[r] < RCUT) nzm |= (1u << r);
        }
    }

    // ---- ballots at the END (no latency exposure mid-gather) ----
    const unsigned lt = (1u << lane) - 1u;
    unsigned bal[4];
    int K = 0;
    #pragma unroll
    for (int r = 0; r < 4; r++) {
        bal[r] = __ballot_sync(0xffffffffu, (nzm >> r) & 1u);
        K += __popc(bal[r]);
    }

    // survivors write ONE compacted float4 each (~K total STS per row)
    {
        int pref = 0;
        #pragma unroll
        for (int r = 0; r < 4; r++) {
            if ((nzm >> r) & 1u) {
                const int p = pref + __popc(bal[r] & lt);
                svec[warp][p] = make_float4(dx4[r], dy4[r], dz4[r], dd4[r]);
            }
            pref += __popc(bal[r]);
        }
    }
    __syncwarp();

    float* orow = out + (long)row * OUTW;

    if (K <= 32) {
        // ---- pass 2: survivors only ----
        float vx = 0.f, vy = 0.f, vz = 0.f;
        unsigned long long k0 = 0ull;
        if (lane < K) {
            const float4 s = svec[warp][lane];
            const float cut = 0.5f * (cospif(s.w * (1.0f / RCUT)) + 1.0f) / s.w; // bit-identical
            vx = cut * s.x; vy = cut * s.y; vz = cut * s.z;
            // ties among nonzero cuts => identical (j,offset) => identical
            // vectors; tie order immaterial -> low bits only need uniqueness.
            k0 = ((unsigned long long)__float_as_uint(cut) << 32) | (unsigned)lane;
        }

        #define CEW(J, UPX) {                                                \
            const bool keepmax = (UPX) ^ ((lane & (J)) != 0);                \
            const unsigned long long o = __shfl_xor_sync(0xffffffffu, k0, (J)); \
            const bool take = keepmax ? (o > k0) : (o < k0);                 \
            k0 = take ? o : k0; }

        if (K <= 8) {
            // 8-wide bitonic (6 CEs); lanes >= 8 carry zeros harmlessly
            { const bool up = ((lane & 2)  == 0); CEW(1, up) }
            { const bool up = ((lane & 4)  == 0); CEW(2, up) CEW(1, up) }
            { const bool up = ((lane & 8)  == 0); CEW(4, up) CEW(2, up) CEW(1, up) }
        } else if (K <= 16) {
            { const bool up = ((lane & 2)  == 0); CEW(1, up) }
            { const bool up = ((lane & 4)  == 0); CEW(2, up) CEW(1, up) }
            { const bool up = ((lane & 8)  == 0); CEW(4, up) CEW(2, up) CEW(1, up) }
            { const bool up = ((lane & 16) == 0); CEW(8, up) CEW(4, up) CEW(2, up) CEW(1, up) }
        } else {
            { const bool up = ((lane & 2)  == 0); CEW(1, up) }
            { const bool up = ((lane & 4)  == 0); CEW(2, up) CEW(1, up) }
            { const bool up = ((lane & 8)  == 0); CEW(4, up) CEW(2, up) CEW(1, up) }
            { const bool up = ((lane & 16) == 0); CEW(8, up) CEW(4, up) CEW(2, up) CEW(1, up) }
            { CEW(16, true) CEW(8, true) CEW(4, true) CEW(2, true) CEW(1, true) }
        }

        // gather sorted vectors via shuffle (source lane = survivor id)
        const int c = (int)(k0 & 63u);
        const float sx = __shfl_sync(0xffffffffu, vx, c);
        const float sy = __shfl_sync(0xffffffffu, vy, c);
        const float sz = __shfl_sync(0xffffffffu, vz, c);
        if (lane < K) {
            stcs_f(orow + 3 * lane + 0, sx);
            stcs_f(orow + 3 * lane + 1, sy);
            stcs_f(orow + 3 * lane + 2, sz);
        }
        // zero-fill [3K, 384): scalar head (lanes 0..2 in parallel), then float4s
        const int start = 3 * K;
        const int f0 = (start + 3) >> 2;
        const int head = 4 * f0 - start;          // 0..3 scalar zeros needed
        if (lane < head) stcs_f(orow + start + lane, 0.0f);
        const float4 z = make_float4(0.f, 0.f, 0.f, 0.f);
        for (int f = f0 + lane; f < OUTW / 4; f += 32)
            stcs_f4(reinterpret_cast<float4*>(orow) + f, z);
    } else {
        fallback_sort_output(&svec[warp][0], K, lane, orow);
    }
}

extern "C" void kernel_launch(void* const* d_in, const int* in_sizes, int n_in,
                              void* d_out, int out_size) {
    const float* positions = (const float*)d_in[0];
    const float* cell      = (const float*)d_in[1];
    const float* offsets   = (const float*)d_in[2];
    const float* mask      = (const float*)d_in[3];
    const int*   neighbors = (const int*)d_in[4];
    float* out = (float*)d_out;

    // coalesced pack pass (triggers programmatic completion immediately)
    pack_positions_kernel<<<(B_ * N_) / 256, 256>>>(positions);

    // main kernel with PDL dependency: launches while pack runs, syncs
    // before reading g_pos4.
    cudaLaunchConfig_t cfg = {};
    cfg.gridDim  = dim3((B_ * N_) / WARPS);
    cfg.blockDim = dim3(128);
    cudaLaunchAttribute attr[1];
    attr[0].id = cudaLaunchAttributeProgrammaticStreamSerialization;
    attr[0].val.programmaticStreamSerializationAllowed = 1;
    cfg.attrs = attr;
    cfg.numAttrs = 1;
    cudaLaunchKernelEx(&cfg, deepmd_angular_kernel,
                       positions, cell, offsets, mask, neighbors, out);
}